// round 17
// baseline (speedup 1.0000x reference)
#include <cuda_runtime.h>
#include <math.h>
#include <stdint.h>

#define B_    16
#define D_    100000
#define M_    128
#define NBIN_ 25
#define G_    27                  // blocks per batch -> 432 total = 3/SM (148 SMs)
#define TOTAL_ (B_ * G_)
#define NSLOT_ 27                 // padded: slot j == bin j-1; slots 0 and 26 are trash
#define NSTAGE_ 3                 // cp.async ring depth per warp
#define RING_F4_ (8 * NSTAGE_ * 128)   // 3072 float4 = 48 KB dynamic smem

// global accumulators — zero at module load; last block re-zeros them each
// run so every graph replay starts from identical state.
__device__ float    g_hla[B_][NBIN_];
__device__ float    g_hll[B_][NBIN_];
__device__ float    g_lsum[B_];
__device__ unsigned g_ticket;

__device__ __forceinline__ void cpasync16(uint32_t saddr, const float4* g) {
    asm volatile("cp.async.cg.shared.global [%0], [%1], 16;" :: "r"(saddr), "l"(g));
}
__device__ __forceinline__ void cp_commit() {
    asm volatile("cp.async.commit_group;");
}
template <int N>
__device__ __forceinline__ void cp_wait() {
    asm volatile("cp.async.wait_group %0;" :: "n"(N));
}

__global__ void __launch_bounds__(256, 3)
qap_fused(const float* __restrict__ qX,
          const float* __restrict__ dXs,
          const int*   __restrict__ labels,
          float*       __restrict__ out) {
    extern __shared__ float4 ring[];     // [warp(8)][stage(3)][128 float4]

    const int b    = blockIdx.y;
    const int tid  = threadIdx.x;
    const int lane = tid & 31;
    const int warp = tid >> 5;
    const int e    = lane & 7;   // float4 slot within row
    const int g    = lane >> 3;  // doc within 4-doc chunk (0..3)

    // per-(warp,doc) private histograms: [warp][doc(4)][arr][NSLOT_]
    __shared__ float s_hist[8 * 4 * 2 * NSLOT_];   // 6.75 KB
    __shared__ float s_wl[8];
    __shared__ int   s_last;

    #pragma unroll
    for (int i = tid; i < 8 * 4 * 2 * NSLOT_; i += 256) s_hist[i] = 0.0f;
    __syncthreads();

    // query slices + 1/|q| via 8-lane group butterfly
    const float4* __restrict__ qf = reinterpret_cast<const float4*>(qX + b * M_);
    const float4 q0 = qf[e], q1 = qf[e + 8], q2 = qf[e + 16], q3 = qf[e + 24];
    float qs = q0.x*q0.x + q0.y*q0.y + q0.z*q0.z + q0.w*q0.w
             + q1.x*q1.x + q1.y*q1.y + q1.z*q1.z + q1.w*q1.w
             + q2.x*q2.x + q2.y*q2.y + q2.z*q2.z + q2.w*q2.w
             + q3.x*q3.x + q3.y*q3.y + q3.z*q3.z + q3.w*q3.w;
    qs += __shfl_xor_sync(0xFFFFFFFFu, qs, 4);
    qs += __shfl_xor_sync(0xFFFFFFFFu, qs, 2);
    qs += __shfl_xor_sync(0xFFFFFFFFu, qs, 1);
    const float inv_qn = rsqrtf(qs);

    const float4* __restrict__ dv = reinterpret_cast<const float4*>(dXs + (size_t)b * D_ * M_);
    const int*    __restrict__ lb = labels + b * D_;

    const int wid     = blockIdx.x * 8 + warp;
    const int stride4 = G_ * 8 * 4;      // 864 docs per sweep
    const int role    = e & 3;           // 0: ha[m0], 1: ha[m1], 2: hl[m0], 3: hl[m1]
    const bool actor  = (e < 4);
    float* const hbase = s_hist + ((warp * 4 + g) * 2 + (role >> 1)) * NSLOT_
                       + (role & 1) + 1;
    float labcnt = 0.0f;

    // per-warp ring base
    float4* const wring = ring + warp * (NSTAGE_ * 128);
    const uint32_t wring_s = (uint32_t)__cvta_generic_to_shared(wring);

    // ---------------- prologue: fill all 3 stages ----------------
    int d0 = wid * 4;                    // < 864 <= D_, every warp has work
    #pragma unroll
    for (int s = 0; s < NSTAGE_; s++) {
        const int dd  = d0 + s * stride4;
        const int ddc = (dd < D_) ? dd : 0;          // clamped (unused if beyond)
        const float4* src = dv + (size_t)ddc * 32;
        const uint32_t dst = wring_s + (uint32_t)(s * 128) * 16u;
        #pragma unroll
        for (int p = 0; p < 4; p++)
            cpasync16(dst + (uint32_t)(p * 32 + lane) * 16u, src + (p * 32 + lane));
        cp_commit();
    }
    int lab = lb[d0 + g];                // depth-1 label prefetch (broadcast)

    // ---------------- main loop ----------------
    int st = 0;
    while (d0 < D_) {
        const int dn   = d0 + stride4;
        const int dpre = (dn < D_) ? dn : 0;

        cp_wait<NSTAGE_ - 1>();          // oldest group (this chunk) complete
        __syncwarp();

        // conflict-free LDS.128: each quarter-warp reads 128 consecutive bytes
        const float4* sp = wring + st * 128 + g * 32;
        const float4 c0 = sp[e], c1 = sp[e + 8], c2 = sp[e + 16], c3 = sp[e + 24];

        float dot = q0.x*c0.x + q0.y*c0.y + q0.z*c0.z + q0.w*c0.w
                  + q1.x*c1.x + q1.y*c1.y + q1.z*c1.z + q1.w*c1.w
                  + q2.x*c2.x + q2.y*c2.y + q2.z*c2.z + q2.w*c2.w
                  + q3.x*c3.x + q3.y*c3.y + q3.z*c3.z + q3.w*c3.w;
        float nr  = c0.x*c0.x + c0.y*c0.y + c0.z*c0.z + c0.w*c0.w
                  + c1.x*c1.x + c1.y*c1.y + c1.z*c1.z + c1.w*c1.w
                  + c2.x*c2.x + c2.y*c2.y + c2.z*c2.z + c2.w*c2.w
                  + c3.x*c3.x + c3.y*c3.y + c3.z*c3.z + c3.w*c3.w;

        // refill the just-consumed stage with chunk d0 + 3*stride (clamped).
        // cp.async smem writes land hundreds of cycles after the 29cyc LDS above.
        {
            const int dp  = d0 + NSTAGE_ * stride4;
            const int dpc = (dp < D_) ? dp : 0;
            const float4* src = dv + (size_t)dpc * 32;
            const uint32_t dst = wring_s + (uint32_t)(st * 128) * 16u;
            #pragma unroll
            for (int p = 0; p < 4; p++)
                cpasync16(dst + (uint32_t)(p * 32 + lane) * 16u, src + (p * 32 + lane));
            cp_commit();
        }
        const int labcur = lab;
        lab = lb[dpre + g];

        // reduce + epilogue run under the prefetch latency
        dot += __shfl_xor_sync(0xFFFFFFFFu, dot, 4);
        nr  += __shfl_xor_sync(0xFFFFFFFFu, nr,  4);
        dot += __shfl_xor_sync(0xFFFFFFFFu, dot, 2);
        nr  += __shfl_xor_sync(0xFFFFFFFFu, nr,  2);
        dot += __shfl_xor_sync(0xFFFFFFFFu, dot, 1);
        nr  += __shfl_xor_sync(0xFFFFFFFFu, nr,  1);

        const float sim = dot * rsqrtf(nr) * inv_qn;    // eps never binds (norms ~11)
        const float t   = (1.0f - sim) * 12.0f;
        const float mf  = floorf(t);
        const int   m0  = (int)mf;                      // in [-1, 24] for any fp edge
        const float fr  = t - mf;
        float w = (role & 1) ? fr : (1.0f - fr);
        if (role & 2) w *= (float)labcur;               // branchless label gate
        if (actor) hbase[m0] += w;                      // LDS+FADD+STS, race-free
        if (e == 0) labcnt += (float)labcur;            // each doc counted once

        st = (st == NSTAGE_ - 1) ? 0 : st + 1;
        d0 = dn;
    }
    cp_wait<0>();                        // drain outstanding copies
    __syncwarp();

    #pragma unroll
    for (int o = 16; o; o >>= 1) labcnt += __shfl_xor_sync(0xFFFFFFFFu, labcnt, o);
    if (lane == 0) s_wl[warp] = labcnt;
    __syncthreads();

    // merge the 32 private copies (bins at slot n+1) into global accumulators
    for (int idx = tid; idx < 2 * NBIN_; idx += 256) {
        const int arr = idx / NBIN_, n = idx % NBIN_;
        float s = 0.0f;
        #pragma unroll
        for (int c = 0; c < 32; c++)
            s += s_hist[(c * 2 + arr) * NSLOT_ + n + 1];
        if (arr) atomicAdd(&g_hll[b][n], s);
        else     atomicAdd(&g_hla[b][n], s);
    }
    if (tid == 0) {
        float s = 0.0f;
        #pragma unroll
        for (int w = 0; w < 8; w++) s += s_wl[w];
        atomicAdd(&g_lsum[b], s);
    }

    __threadfence();
    __syncthreads();
    if (tid == 0) {
        unsigned prev = atomicAdd(&g_ticket, 1u);
        s_last = (prev == TOTAL_ - 1u);
    }
    __syncthreads();
    if (!s_last) return;

    // ---------------- last block: finalize + reset state ----------------
    __shared__ float f_hl[B_][NBIN_];
    __shared__ float f_ha[B_][NBIN_];
    __shared__ float f_ls[B_];

    for (int idx = tid; idx < B_ * NBIN_; idx += 256) {
        const int bb = idx / NBIN_, n = idx % NBIN_;
        f_hl[bb][n] = __ldcg(&g_hll[bb][n]);
        f_ha[bb][n] = __ldcg(&g_hla[bb][n]);
        g_hll[bb][n] = 0.0f;
        g_hla[bb][n] = 0.0f;
    }
    if (tid < B_) {
        f_ls[tid] = __ldcg(&g_lsum[tid]);
        g_lsum[tid] = 0.0f;
    }
    __syncthreads();

    float apq = 0.0f;
    if (tid < B_) {
        float cl = 0.0f, ca = 0.0f, s = 0.0f;
        const float inv_lab = 1.0f / f_ls[tid];
        #pragma unroll
        for (int n = 0; n < NBIN_; n++) {
            const float vhl = f_hl[tid][n];
            cl += vhl;
            ca += f_ha[tid][n];
            s += (cl / (ca + 1e-16f)) * (vhl * inv_lab);
        }
        apq = s / (float)NBIN_;
    }
    if (tid < 32) {
        #pragma unroll
        for (int o = 16; o; o >>= 1) apq += __shfl_xor_sync(0xFFFFFFFFu, apq, o);
        if (tid == 0) {
            out[0] = apq / (float)B_;
            g_ticket = 0u;
        }
    }
}

extern "C" void kernel_launch(void* const* d_in, const int* in_sizes, int n_in,
                              void* d_out, int out_size) {
    const float* qX     = (const float*)d_in[0];
    const float* dXs    = (const float*)d_in[1];
    const int*   labels = (const int*)d_in[2];
    float*       out    = (float*)d_out;

    const int dynsmem = RING_F4_ * (int)sizeof(float4);   // 48 KB
    // opt-in so dynamic+static > 48 KB default limit is launchable
    // (host attribute set; idempotent; not a stream operation)
    cudaFuncSetAttribute(qap_fused, cudaFuncAttributeMaxDynamicSharedMemorySize, dynsmem);
    qap_fused<<<dim3(G_, B_), 256, dynsmem>>>(qX, dXs, labels, out);
}